// round 1
// baseline (speedup 1.0000x reference)
#include <cuda_runtime.h>
#include <math.h>
#include <stdint.h>

// ---------------- problem constants ----------------
constexpr int NN  = 50000;
constexpr int EE  = 800000;
constexpr int IN_ = 256;
constexpr int HD  = 256;
constexpr int BB  = 256;
constexpr int ND  = 5000;
constexpr int KK  = 16;
constexpr int ER  = 20000;

// ---------------- device scratch (no allocs allowed) ----------------
__device__ float g_h[(size_t)NN * HD];     // GEMM output of current layer
__device__ float g_act[(size_t)NN * HD];   // layer-1 activated output (GEMM2 input)
__device__ float g_emb[(size_t)NN * HD];   // final node embeddings (modified by scan)
__device__ float g_ssrc[NN];
__device__ float g_sdst[NN];
__device__ int   g_deg[NN];
__device__ int   g_cursor[NN];
__device__ int   g_rowptr[NN + 1];
__device__ int   g_csr_src[EE];
__device__ int   g_cnt[3 * ND];

// ---------------- small utility kernels ----------------
__global__ void zero_kernel() {
    int i = blockIdx.x * blockDim.x + threadIdx.x;
    if (i < NN) { g_deg[i] = 0; g_cursor[i] = 0; }
    if (i < 3 * ND) g_cnt[i] = 0;
}

__global__ void hist_deg_kernel(const int* __restrict__ dst) {
    int e = blockIdx.x * blockDim.x + threadIdx.x;
    if (e < EE) atomicAdd(&g_deg[dst[e]], 1);
}

__global__ void cnt_hist_kernel(const int* __restrict__ res) {
    int i = blockIdx.x * blockDim.x + threadIdx.x;
    if (i < 3 * ER) {
        int row = i / ER;
        atomicAdd(&g_cnt[row * ND + res[i]], 1);
    }
}

// single-block exclusive prefix sum of g_deg -> g_rowptr
__global__ void prefix_kernel() {
    __shared__ int sums[1024];
    int tid = threadIdx.x;
    const int CH = (NN + 1023) / 1024;  // 49
    int start = tid * CH;
    int local = 0;
    for (int i = 0; i < CH; i++) {
        int idx = start + i;
        if (idx < NN) local += g_deg[idx];
    }
    sums[tid] = local;
    __syncthreads();
    for (int off = 1; off < 1024; off <<= 1) {
        int v = (tid >= off) ? sums[tid - off] : 0;
        __syncthreads();
        sums[tid] += v;
        __syncthreads();
    }
    int run = (tid == 0) ? 0 : sums[tid - 1];
    for (int i = 0; i < CH; i++) {
        int idx = start + i;
        if (idx < NN) { g_rowptr[idx] = run; run += g_deg[idx]; }
    }
    if (tid == 1023) g_rowptr[NN] = sums[1023];
}

__global__ void scatter_kernel(const int* __restrict__ src, const int* __restrict__ dst) {
    int e = blockIdx.x * blockDim.x + threadIdx.x;
    if (e < EE) {
        int d = dst[e];
        int pos = atomicAdd(&g_cursor[d], 1);
        g_csr_src[g_rowptr[d] + pos] = src[e];
    }
}

// ---------------- SGEMM with packed f32x2 FMA ----------------
// C[M,256] = A[M,256] @ W[256,256], C = g_h
// LAYER==1: A = Ain (param).  LAYER==2: A = g_act.
template <int LAYER>
__global__ __launch_bounds__(256) void gemm_kernel(const float* __restrict__ Ain,
                                                   const float* __restrict__ W, int M) {
    const float* __restrict__ A = (LAYER == 1) ? Ain : (const float*)g_act;

    __shared__ float As[16][128 + 4];  // transposed A tile, stride 132 (16B aligned)
    __shared__ float Bs[16][128];

    int tid = threadIdx.x;
    int tx = tid & 15;       // 0..15 -> N
    int ty = tid >> 4;       // 0..15 -> M
    int row0 = blockIdx.x * 128;
    int col0 = blockIdx.y * 128;

    unsigned long long acc[8][4];
#pragma unroll
    for (int i = 0; i < 8; i++)
#pragma unroll
        for (int j = 0; j < 4; j++) acc[i][j] = 0ull;

    for (int k0 = 0; k0 < 256; k0 += 16) {
        // load A tile 128x16 (transposed into As)
#pragma unroll
        for (int i = 0; i < 2; i++) {
            int id = tid + 256 * i;          // 0..511
            int r = id >> 2;                  // 0..127
            int c4 = (id & 3) * 4;            // 0,4,8,12
            float4 v = make_float4(0.f, 0.f, 0.f, 0.f);
            int gr = row0 + r;
            if (gr < M) v = *(const float4*)(A + (size_t)gr * 256 + k0 + c4);
            As[c4 + 0][r] = v.x; As[c4 + 1][r] = v.y;
            As[c4 + 2][r] = v.z; As[c4 + 3][r] = v.w;
        }
        // load B tile 16x128
#pragma unroll
        for (int i = 0; i < 2; i++) {
            int id = tid + 256 * i;
            int r = id >> 5;                  // 0..15
            int c4 = (id & 31) * 4;
            *(float4*)&Bs[r][c4] = *(const float4*)(W + (size_t)(k0 + r) * 256 + col0 + c4);
        }
        __syncthreads();

#pragma unroll
        for (int k = 0; k < 16; k++) {
            float a[8];
            *(float4*)&a[0] = *(const float4*)&As[k][ty * 8];
            *(float4*)&a[4] = *(const float4*)&As[k][ty * 8 + 4];
            unsigned long long b2[4];
            const unsigned long long* bp = (const unsigned long long*)&Bs[k][tx * 8];
            b2[0] = bp[0]; b2[1] = bp[1]; b2[2] = bp[2]; b2[3] = bp[3];
            unsigned long long a2[8];
#pragma unroll
            for (int i = 0; i < 8; i++)
                asm("mov.b64 %0, {%1, %1};" : "=l"(a2[i]) : "f"(a[i]));
#pragma unroll
            for (int i = 0; i < 8; i++)
#pragma unroll
                for (int j = 0; j < 4; j++)
                    asm("fma.rn.f32x2 %0, %1, %2, %0;"
                        : "+l"(acc[i][j]) : "l"(a2[i]), "l"(b2[j]));
        }
        __syncthreads();
    }

#pragma unroll
    for (int i = 0; i < 8; i++) {
        int row = row0 + ty * 8 + i;
        if (row < M) {
            union { unsigned long long u[2]; float4 v; } c0, c1;
            c0.u[0] = acc[i][0]; c0.u[1] = acc[i][1];
            c1.u[0] = acc[i][2]; c1.u[1] = acc[i][3];
            float4* d = (float4*)(g_h + (size_t)row * 256 + col0 + tx * 8);
            d[0] = c0.v; d[1] = c1.v;
        }
    }
}

// ---------------- per-node attention dot products ----------------
__global__ __launch_bounds__(256) void sdots_kernel(const float* __restrict__ asrc,
                                                    const float* __restrict__ adst) {
    int w = (blockIdx.x * blockDim.x + threadIdx.x) >> 5;
    int lane = threadIdx.x & 31;
    if (w >= NN) return;
    const float4* hp = (const float4*)(g_h + (size_t)w * 256);
    const float4* as4 = (const float4*)asrc;
    const float4* ad4 = (const float4*)adst;
    float4 v0 = hp[lane], v1 = hp[32 + lane];
    float4 a0 = as4[lane], a1 = as4[32 + lane];
    float4 d0 = ad4[lane], d1 = ad4[32 + lane];
    float s1 = v0.x * a0.x + v0.y * a0.y + v0.z * a0.z + v0.w * a0.w
             + v1.x * a1.x + v1.y * a1.y + v1.z * a1.z + v1.w * a1.w;
    float s2 = v0.x * d0.x + v0.y * d0.y + v0.z * d0.z + v0.w * d0.w
             + v1.x * d1.x + v1.y * d1.y + v1.z * d1.z + v1.w * d1.w;
#pragma unroll
    for (int o = 16; o; o >>= 1) {
        s1 += __shfl_xor_sync(0xffffffffu, s1, o);
        s2 += __shfl_xor_sync(0xffffffffu, s2, o);
    }
    if (lane == 0) { g_ssrc[w] = s1; g_sdst[w] = s2; }
}

// ---------------- fused GAT softmax + aggregation, warp per dst ----------------
__device__ __forceinline__ float leaky02(float s) { return s > 0.f ? s : 0.2f * s; }

template <int LAYER>  // LAYER==1: out=g_act with silu; LAYER==2: out=g_emb no act
__global__ __launch_bounds__(256) void gat_aggregate_kernel(const float* __restrict__ bias) {
    int w = (blockIdx.x * blockDim.x + threadIdx.x) >> 5;
    int lane = threadIdx.x & 31;
    if (w >= NN) return;

    int base = g_rowptr[w];
    int d = g_rowptr[w + 1] - base;
    float4 acc0 = make_float4(0.f, 0.f, 0.f, 0.f);
    float4 acc1 = make_float4(0.f, 0.f, 0.f, 0.f);

    if (d > 0) {
        float sd = g_sdst[w];
        float mx = -1e30f;
        for (int i = lane; i < d; i += 32) {
            float e = leaky02(g_ssrc[g_csr_src[base + i]] + sd);
            mx = fmaxf(mx, e);
        }
#pragma unroll
        for (int o = 16; o; o >>= 1) mx = fmaxf(mx, __shfl_xor_sync(0xffffffffu, mx, o));
        float z = 0.f;
        for (int i = lane; i < d; i += 32) {
            float e = leaky02(g_ssrc[g_csr_src[base + i]] + sd);
            z += __expf(e - mx);
        }
#pragma unroll
        for (int o = 16; o; o >>= 1) z += __shfl_xor_sync(0xffffffffu, z, o);
        float invz = 1.f / (z + 1e-16f);

#pragma unroll 2
        for (int i = 0; i < d; i++) {
            int src = g_csr_src[base + i];
            float e = leaky02(g_ssrc[src] + sd);
            float a = __expf(e - mx) * invz;
            const float4* hp = (const float4*)(g_h + (size_t)src * 256);
            float4 v0 = hp[lane];
            float4 v1 = hp[32 + lane];
            acc0.x += a * v0.x; acc0.y += a * v0.y; acc0.z += a * v0.z; acc0.w += a * v0.w;
            acc1.x += a * v1.x; acc1.y += a * v1.y; acc1.z += a * v1.z; acc1.w += a * v1.w;
        }
    }

    const float4* b4 = (const float4*)bias;
    float4 bb0 = b4[lane], bb1 = b4[32 + lane];
    acc0.x += bb0.x; acc0.y += bb0.y; acc0.z += bb0.z; acc0.w += bb0.w;
    acc1.x += bb1.x; acc1.y += bb1.y; acc1.z += bb1.z; acc1.w += bb1.w;

    if (LAYER == 1) {
        acc0.x = acc0.x / (1.f + __expf(-acc0.x));
        acc0.y = acc0.y / (1.f + __expf(-acc0.y));
        acc0.z = acc0.z / (1.f + __expf(-acc0.z));
        acc0.w = acc0.w / (1.f + __expf(-acc0.w));
        acc1.x = acc1.x / (1.f + __expf(-acc1.x));
        acc1.y = acc1.y / (1.f + __expf(-acc1.y));
        acc1.z = acc1.z / (1.f + __expf(-acc1.z));
        acc1.w = acc1.w / (1.f + __expf(-acc1.w));
    }
    float* outp = (LAYER == 1) ? g_act : g_emb;
    float4* o4 = (float4*)(outp + (size_t)w * 256);
    o4[lane] = acc0;
    o4[32 + lane] = acc1;
}

// ---------------- sequential per-triplet scan (column-owned, no barriers) ----------
__global__ void scan_seq_kernel(const int* __restrict__ head, const int* __restrict__ rel,
                                const int* __restrict__ g2l, const int* __restrict__ nb,
                                const float* __restrict__ wts) {
    int tid = threadIdx.x;  // 256 threads; thread owns column tid
    for (int t = 0; t < BB; t++) {
        int r = rel[t];
        if (r < 4 || r > 6) continue;
        int hi = head[t];
        int local = g2l[hi];
        int ridx = r - 4;
        float deg = (float)g_cnt[ridx * ND + local];
        float c = 0.7f * __expf(-0.7f * deg) + 0.2f;
        float vec = 0.f;
#pragma unroll
        for (int k = 0; k < KK; k++) {
            int n = nb[local * KK + k];
            vec += wts[local * KK + k] * g_emb[(size_t)n * 256 + tid];
        }
        float cur = g_emb[(size_t)hi * 256 + tid];
        g_emb[(size_t)hi * 256 + tid] = c * vec + (1.f - c) * cur;
    }
}

// ---------------- DistMult decode + sigmoid ----------------
__global__ __launch_bounds__(256) void decode_kernel(const int* __restrict__ head,
                                                     const int* __restrict__ rel,
                                                     const int* __restrict__ tail,
                                                     const float* __restrict__ rel_emb,
                                                     float* __restrict__ out) {
    int w = (blockIdx.x * blockDim.x + threadIdx.x) >> 5;
    int lane = threadIdx.x & 31;
    if (w >= BB) return;
    int hi = head[w], ti = tail[w], r = rel[w];
    const float4* hp = (const float4*)(g_emb + (size_t)hi * 256);
    const float4* tp = (const float4*)(g_emb + (size_t)ti * 256);
    const float4* rp = (const float4*)(rel_emb + (size_t)r * 256);
    float4 h0 = hp[lane], h1 = hp[32 + lane];
    float4 t0 = tp[lane], t1 = tp[32 + lane];
    float4 r0 = rp[lane], r1 = rp[32 + lane];
    float s = h0.x * r0.x * t0.x + h0.y * r0.y * t0.y + h0.z * r0.z * t0.z + h0.w * r0.w * t0.w
            + h1.x * r1.x * t1.x + h1.y * r1.y * t1.y + h1.z * r1.z * t1.z + h1.w * r1.w * t1.w;
#pragma unroll
    for (int o = 16; o; o >>= 1) s += __shfl_xor_sync(0xffffffffu, s, o);
    if (lane == 0) out[w] = 1.f / (1.f + __expf(-s));
}

// ---------------- host launch ----------------
extern "C" void kernel_launch(void* const* d_in, const int* in_sizes, int n_in,
                              void* d_out, int out_size) {
    const float* x        = (const float*)d_in[0];
    const int*   eidx     = (const int*)d_in[1];
    const int*   head     = (const int*)d_in[2];
    const int*   rel      = (const int*)d_in[3];
    const int*   tail     = (const int*)d_in[4];
    const int*   g2l      = (const int*)d_in[5];
    const int*   reledge  = (const int*)d_in[6];
    const int*   simnb    = (const int*)d_in[7];
    const float* simw     = (const float*)d_in[8];
    const float* W1       = (const float*)d_in[9];
    const float* a1s      = (const float*)d_in[10];
    const float* a1d      = (const float*)d_in[11];
    const float* b1       = (const float*)d_in[12];
    const float* W2       = (const float*)d_in[13];
    const float* a2s      = (const float*)d_in[14];
    const float* a2d      = (const float*)d_in[15];
    const float* b2       = (const float*)d_in[16];
    const float* rel_emb  = (const float*)d_in[17];
    float* out = (float*)d_out;

    const int* src = eidx;
    const int* dst = eidx + EE;

    // CSR build (shared by both layers) + disease-degree histogram
    zero_kernel<<<(NN + 255) / 256, 256>>>();
    hist_deg_kernel<<<(EE + 255) / 256, 256>>>(dst);
    cnt_hist_kernel<<<(3 * ER + 255) / 256, 256>>>(reledge);
    prefix_kernel<<<1, 1024>>>();
    scatter_kernel<<<(EE + 255) / 256, 256>>>(src, dst);

    dim3 ggrid((NN + 127) / 128, 2);
    int nwBlocks = (NN * 32 + 255) / 256;  // warp-per-node kernels

    // Layer 1: GEMM -> dots -> fused softmax-aggregate (+bias+silu)
    gemm_kernel<1><<<ggrid, 256>>>(x, W1, NN);
    sdots_kernel<<<nwBlocks, 256>>>(a1s, a1d);
    gat_aggregate_kernel<1><<<nwBlocks, 256>>>(b1);

    // Layer 2
    gemm_kernel<2><<<ggrid, 256>>>(nullptr, W2, NN);
    sdots_kernel<<<nwBlocks, 256>>>(a2s, a2d);
    gat_aggregate_kernel<2><<<nwBlocks, 256>>>(b2);

    // Sequential disease-embedding modification + decode
    scan_seq_kernel<<<1, 256>>>(head, rel, g2l, simnb, simw);
    decode_kernel<<<(BB * 32 + 255) / 256, 256>>>(head, rel, tail, rel_emb, out);
}

// round 2
// speedup vs baseline: 1.1746x; 1.1746x over previous
#include <cuda_runtime.h>
#include <cuda_bf16.h>
#include <mma.h>
#include <math.h>
#include <stdint.h>

using namespace nvcuda;

// ---------------- problem constants ----------------
constexpr int NN  = 50000;
constexpr int EE  = 800000;
constexpr int HD  = 256;
constexpr int BB  = 256;
constexpr int ND  = 5000;
constexpr int KK  = 16;
constexpr int ER  = 20000;

// ---------------- device scratch (no allocs allowed) ----------------
__device__ __align__(16) float g_h[(size_t)NN * HD];     // GEMM output of current layer
__device__ __align__(16) float g_act[(size_t)NN * HD];   // layer-1 activated output
__device__ __align__(16) float g_emb[(size_t)NN * HD];   // final node embeddings
__device__ float g_ssrc[NN];
__device__ float g_sdst[NN];
__device__ int   g_deg[NN];
__device__ int   g_cursor[NN];
__device__ int   g_rowptr[NN + 1];
__device__ int   g_csr_src[EE];
__device__ int   g_cnt[3 * ND];

constexpr int PB = 128;                    // prefix partition blocks
constexpr int CHUNK = (NN + PB - 1) / PB;  // 391
__device__ int g_part[PB];

// ---------------- small utility kernels ----------------
__global__ void zero_kernel() {
    int i = blockIdx.x * blockDim.x + threadIdx.x;
    if (i < NN) { g_deg[i] = 0; g_cursor[i] = 0; }
    if (i < 3 * ND) g_cnt[i] = 0;
    if (i == 0) g_rowptr[NN] = EE;
}

__global__ void hist_deg_kernel(const int* __restrict__ dst) {
    int e = blockIdx.x * blockDim.x + threadIdx.x;
    if (e < EE) atomicAdd(&g_deg[dst[e]], 1);
}

__global__ void cnt_hist_kernel(const int* __restrict__ res) {
    int i = blockIdx.x * blockDim.x + threadIdx.x;
    if (i < 3 * ER) {
        int row = i / ER;
        atomicAdd(&g_cnt[row * ND + res[i]], 1);
    }
}

// per-partition sums
__global__ void partial_kernel() {
    __shared__ int sh[256];
    int b = blockIdx.x, t = threadIdx.x;
    int base = b * CHUNK;
    int s = 0;
    for (int i = t; i < CHUNK; i += 256) {
        int idx = base + i;
        if (idx < NN) s += g_deg[idx];
    }
    sh[t] = s;
    __syncthreads();
    for (int off = 128; off; off >>= 1) {
        if (t < off) sh[t] += sh[t + off];
        __syncthreads();
    }
    if (t == 0) g_part[b] = sh[0];
}

// per-partition exclusive scan with base from g_part
__global__ void rowptr_kernel() {
    __shared__ int red[128];
    __shared__ int s[512];
    int b = blockIdx.x, t = threadIdx.x;  // 512 threads
    if (t < 128) red[t] = (t < b) ? g_part[t] : 0;
    __syncthreads();
    for (int off = 64; off; off >>= 1) {
        if (t < off) red[t] += red[t + off];
        __syncthreads();
    }
    int base = red[0];
    int idx = b * CHUNK + t;
    int v = (t < CHUNK && idx < NN) ? g_deg[idx] : 0;
    s[t] = v;
    __syncthreads();
    for (int off = 1; off < 512; off <<= 1) {
        int u = (t >= off) ? s[t - off] : 0;
        __syncthreads();
        s[t] += u;
        __syncthreads();
    }
    if (t < CHUNK && idx < NN) g_rowptr[idx] = base + s[t] - v;
}

__global__ void scatter_kernel(const int* __restrict__ src, const int* __restrict__ dst) {
    int e = blockIdx.x * blockDim.x + threadIdx.x;
    if (e < EE) {
        int d = dst[e];
        int pos = atomicAdd(&g_cursor[d], 1);
        g_csr_src[g_rowptr[d] + pos] = src[e];
    }
}

// ---------------- bf16 split tensor-core GEMM (3xBF16 compensation) ----------------
// C[M,256] = A[M,256] @ W[256,256] in ~fp32 accuracy.
// hi = bf16(x), lo = bf16(x - hi); C = Ahi*Whi + Ahi*Wlo + Alo*Whi.
constexpr int BM = 128, BN = 128, KC = 32;
constexpr int LDA = KC + 8;   // 40 halves
constexpr int LDB = BN + 8;   // 136 halves

template <int LAYER>
__global__ __launch_bounds__(256) void gemm_tc(const float* __restrict__ Ain,
                                               const float* __restrict__ W, int M) {
    const float* __restrict__ A = (LAYER == 1) ? Ain : (const float*)g_act;

    __shared__ alignas(32) __nv_bfloat16 Ah[BM][LDA];
    __shared__ alignas(32) __nv_bfloat16 Al[BM][LDA];
    __shared__ alignas(32) __nv_bfloat16 Bh[KC][LDB];
    __shared__ alignas(32) __nv_bfloat16 Bl[KC][LDB];

    int tid = threadIdx.x;
    int wid = tid >> 5, lane = tid & 31;
    int wm = wid & 3;        // 0..3 -> 32-row stripes
    int wn = wid >> 2;       // 0..1 -> 64-col stripes
    int row0 = blockIdx.x * BM;
    int col0 = blockIdx.y * BN;

    wmma::fragment<wmma::accumulator, 16, 16, 16, float> acc[2][4];
#pragma unroll
    for (int mt = 0; mt < 2; mt++)
#pragma unroll
        for (int nt = 0; nt < 4; nt++) wmma::fill_fragment(acc[mt][nt], 0.0f);

    for (int kc = 0; kc < 256; kc += KC) {
        // A tile: 128 rows x 32 k. 8 threads/row, 4 passes of 32 rows.
        {
            int r = tid >> 3;
            int kq = (tid & 7) * 4;
#pragma unroll
            for (int p = 0; p < 4; p++) {
                int rr = r + p * 32;
                int gr = row0 + rr;
                if (gr >= M) gr = M - 1;  // clamp; OOB rows never stored
                float4 v = *(const float4*)(A + (size_t)gr * 256 + kc + kq);
                float f[4] = {v.x, v.y, v.z, v.w};
#pragma unroll
                for (int j = 0; j < 4; j++) {
                    __nv_bfloat16 h = __float2bfloat16(f[j]);
                    Ah[rr][kq + j] = h;
                    Al[rr][kq + j] = __float2bfloat16(f[j] - __bfloat162float(h));
                }
            }
        }
        // B tile: 32 k x 128 n. 32 threads/row, 4 passes of 8 k-rows.
        {
            int kr = tid >> 5;
            int n4 = (tid & 31) * 4;
#pragma unroll
            for (int p = 0; p < 4; p++) {
                int kk = kr + p * 8;
                float4 v = *(const float4*)(W + (size_t)(kc + kk) * 256 + col0 + n4);
                float f[4] = {v.x, v.y, v.z, v.w};
#pragma unroll
                for (int j = 0; j < 4; j++) {
                    __nv_bfloat16 h = __float2bfloat16(f[j]);
                    Bh[kk][n4 + j] = h;
                    Bl[kk][n4 + j] = __float2bfloat16(f[j] - __bfloat162float(h));
                }
            }
        }
        __syncthreads();

#pragma unroll
        for (int s = 0; s < KC / 16; s++) {
            wmma::fragment<wmma::matrix_a, 16, 16, 16, __nv_bfloat16, wmma::row_major> ah[2], al[2];
#pragma unroll
            for (int mt = 0; mt < 2; mt++) {
                wmma::load_matrix_sync(ah[mt], &Ah[wm * 32 + mt * 16][s * 16], LDA);
                wmma::load_matrix_sync(al[mt], &Al[wm * 32 + mt * 16][s * 16], LDA);
            }
#pragma unroll
            for (int nt = 0; nt < 4; nt++) {
                wmma::fragment<wmma::matrix_b, 16, 16, 16, __nv_bfloat16, wmma::row_major> bh, bl;
                wmma::load_matrix_sync(bh, &Bh[s * 16][wn * 64 + nt * 16], LDB);
                wmma::load_matrix_sync(bl, &Bl[s * 16][wn * 64 + nt * 16], LDB);
#pragma unroll
                for (int mt = 0; mt < 2; mt++) {
                    wmma::mma_sync(acc[mt][nt], ah[mt], bh, acc[mt][nt]);
                    wmma::mma_sync(acc[mt][nt], ah[mt], bl, acc[mt][nt]);
                    wmma::mma_sync(acc[mt][nt], al[mt], bh, acc[mt][nt]);
                }
            }
        }
        __syncthreads();
    }

    // store (after final __syncthreads, shared is free for staging)
    int mrow = row0 + wm * 32;
    int ncol = col0 + wn * 64;
#pragma unroll
    for (int mt = 0; mt < 2; mt++) {
        int rbase = mrow + mt * 16;
#pragma unroll
        for (int nt = 0; nt < 4; nt++) {
            if (rbase + 16 <= M) {
                wmma::store_matrix_sync(g_h + (size_t)rbase * 256 + ncol + nt * 16,
                                        acc[mt][nt], 256, wmma::mem_row_major);
            } else if (rbase < M) {
                float* stg = ((float*)&Ah[0][0]) + wid * 320;  // 16x20 per warp
                wmma::store_matrix_sync(stg, acc[mt][nt], 20, wmma::mem_row_major);
                __syncwarp();
                for (int i = lane; i < 256; i += 32) {
                    int rr = i >> 4, cc = i & 15;
                    if (rbase + rr < M)
                        g_h[(size_t)(rbase + rr) * 256 + ncol + nt * 16 + cc] = stg[rr * 20 + cc];
                }
                __syncwarp();
            }
        }
    }
}

// ---------------- per-node attention dot products ----------------
__global__ __launch_bounds__(256) void sdots_kernel(const float* __restrict__ asrc,
                                                    const float* __restrict__ adst) {
    int w = (blockIdx.x * blockDim.x + threadIdx.x) >> 5;
    int lane = threadIdx.x & 31;
    if (w >= NN) return;
    const float4* hp = (const float4*)(g_h + (size_t)w * 256);
    const float4* as4 = (const float4*)asrc;
    const float4* ad4 = (const float4*)adst;
    float4 v0 = hp[lane], v1 = hp[32 + lane];
    float4 a0 = as4[lane], a1 = as4[32 + lane];
    float4 d0 = ad4[lane], d1 = ad4[32 + lane];
    float s1 = v0.x * a0.x + v0.y * a0.y + v0.z * a0.z + v0.w * a0.w
             + v1.x * a1.x + v1.y * a1.y + v1.z * a1.z + v1.w * a1.w;
    float s2 = v0.x * d0.x + v0.y * d0.y + v0.z * d0.z + v0.w * d0.w
             + v1.x * d1.x + v1.y * d1.y + v1.z * d1.z + v1.w * d1.w;
#pragma unroll
    for (int o = 16; o; o >>= 1) {
        s1 += __shfl_xor_sync(0xffffffffu, s1, o);
        s2 += __shfl_xor_sync(0xffffffffu, s2, o);
    }
    if (lane == 0) { g_ssrc[w] = s1; g_sdst[w] = s2; }
}

// ---------------- fused GAT softmax + aggregation, warp per dst ----------------
__device__ __forceinline__ float leaky02(float s) { return s > 0.f ? s : 0.2f * s; }

template <int LAYER>  // LAYER==1: out=g_act with silu; LAYER==2: out=g_emb no act
__global__ __launch_bounds__(256) void gat_aggregate_kernel(const float* __restrict__ bias) {
    int w = (blockIdx.x * blockDim.x + threadIdx.x) >> 5;
    int lane = threadIdx.x & 31;
    if (w >= NN) return;

    int base = g_rowptr[w];
    int d = g_rowptr[w + 1] - base;
    float4 acc0 = make_float4(0.f, 0.f, 0.f, 0.f);
    float4 acc1 = make_float4(0.f, 0.f, 0.f, 0.f);

    if (d > 0) {
        float sd = g_sdst[w];
        float mx = -1e30f;
        for (int i = lane; i < d; i += 32) {
            float e = leaky02(g_ssrc[g_csr_src[base + i]] + sd);
            mx = fmaxf(mx, e);
        }
#pragma unroll
        for (int o = 16; o; o >>= 1) mx = fmaxf(mx, __shfl_xor_sync(0xffffffffu, mx, o));
        float z = 0.f;
        for (int i = lane; i < d; i += 32) {
            float e = leaky02(g_ssrc[g_csr_src[base + i]] + sd);
            z += __expf(e - mx);
        }
#pragma unroll
        for (int o = 16; o; o >>= 1) z += __shfl_xor_sync(0xffffffffu, z, o);
        float invz = 1.f / (z + 1e-16f);

#pragma unroll 2
        for (int i = 0; i < d; i++) {
            int src = g_csr_src[base + i];
            float e = leaky02(g_ssrc[src] + sd);
            float a = __expf(e - mx) * invz;
            const float4* hp = (const float4*)(g_h + (size_t)src * 256);
            float4 v0 = hp[lane];
            float4 v1 = hp[32 + lane];
            acc0.x += a * v0.x; acc0.y += a * v0.y; acc0.z += a * v0.z; acc0.w += a * v0.w;
            acc1.x += a * v1.x; acc1.y += a * v1.y; acc1.z += a * v1.z; acc1.w += a * v1.w;
        }
    }

    const float4* b4 = (const float4*)bias;
    float4 bb0 = b4[lane], bb1 = b4[32 + lane];
    acc0.x += bb0.x; acc0.y += bb0.y; acc0.z += bb0.z; acc0.w += bb0.w;
    acc1.x += bb1.x; acc1.y += bb1.y; acc1.z += bb1.z; acc1.w += bb1.w;

    if (LAYER == 1) {
        acc0.x = acc0.x / (1.f + __expf(-acc0.x));
        acc0.y = acc0.y / (1.f + __expf(-acc0.y));
        acc0.z = acc0.z / (1.f + __expf(-acc0.z));
        acc0.w = acc0.w / (1.f + __expf(-acc0.w));
        acc1.x = acc1.x / (1.f + __expf(-acc1.x));
        acc1.y = acc1.y / (1.f + __expf(-acc1.y));
        acc1.z = acc1.z / (1.f + __expf(-acc1.z));
        acc1.w = acc1.w / (1.f + __expf(-acc1.w));
    }
    float* outp = (LAYER == 1) ? g_act : g_emb;
    float4* o4 = (float4*)(outp + (size_t)w * 256);
    o4[lane] = acc0;
    o4[32 + lane] = acc1;
}

// ---------------- sequential per-triplet scan (column-owned, no barriers) ----------
__global__ void scan_seq_kernel(const int* __restrict__ head, const int* __restrict__ rel,
                                const int* __restrict__ g2l, const int* __restrict__ nb,
                                const float* __restrict__ wts) {
    int tid = threadIdx.x;  // 256 threads; thread owns column tid
    for (int t = 0; t < BB; t++) {
        int r = rel[t];
        if (r < 4 || r > 6) continue;
        int hi = head[t];
        int local = g2l[hi];
        int ridx = r - 4;
        float deg = (float)g_cnt[ridx * ND + local];
        float c = 0.7f * __expf(-0.7f * deg) + 0.2f;
        float vec = 0.f;
#pragma unroll
        for (int k = 0; k < KK; k++) {
            int n = nb[local * KK + k];
            vec += wts[local * KK + k] * g_emb[(size_t)n * 256 + tid];
        }
        float cur = g_emb[(size_t)hi * 256 + tid];
        g_emb[(size_t)hi * 256 + tid] = c * vec + (1.f - c) * cur;
    }
}

// ---------------- DistMult decode + sigmoid ----------------
__global__ __launch_bounds__(256) void decode_kernel(const int* __restrict__ head,
                                                     const int* __restrict__ rel,
                                                     const int* __restrict__ tail,
                                                     const float* __restrict__ rel_emb,
                                                     float* __restrict__ out) {
    int w = (blockIdx.x * blockDim.x + threadIdx.x) >> 5;
    int lane = threadIdx.x & 31;
    if (w >= BB) return;
    int hi = head[w], ti = tail[w], r = rel[w];
    const float4* hp = (const float4*)(g_emb + (size_t)hi * 256);
    const float4* tp = (const float4*)(g_emb + (size_t)ti * 256);
    const float4* rp = (const float4*)(rel_emb + (size_t)r * 256);
    float4 h0 = hp[lane], h1 = hp[32 + lane];
    float4 t0 = tp[lane], t1 = tp[32 + lane];
    float4 r0 = rp[lane], r1 = rp[32 + lane];
    float s = h0.x * r0.x * t0.x + h0.y * r0.y * t0.y + h0.z * r0.z * t0.z + h0.w * r0.w * t0.w
            + h1.x * r1.x * t1.x + h1.y * r1.y * t1.y + h1.z * r1.z * t1.z + h1.w * r1.w * t1.w;
#pragma unroll
    for (int o = 16; o; o >>= 1) s += __shfl_xor_sync(0xffffffffu, s, o);
    if (lane == 0) out[w] = 1.f / (1.f + __expf(-s));
}

// ---------------- host launch ----------------
extern "C" void kernel_launch(void* const* d_in, const int* in_sizes, int n_in,
                              void* d_out, int out_size) {
    const float* x        = (const float*)d_in[0];
    const int*   eidx     = (const int*)d_in[1];
    const int*   head     = (const int*)d_in[2];
    const int*   rel      = (const int*)d_in[3];
    const int*   tail     = (const int*)d_in[4];
    const int*   g2l      = (const int*)d_in[5];
    const int*   reledge  = (const int*)d_in[6];
    const int*   simnb    = (const int*)d_in[7];
    const float* simw     = (const float*)d_in[8];
    const float* W1       = (const float*)d_in[9];
    const float* a1s      = (const float*)d_in[10];
    const float* a1d      = (const float*)d_in[11];
    const float* b1       = (const float*)d_in[12];
    const float* W2       = (const float*)d_in[13];
    const float* a2s      = (const float*)d_in[14];
    const float* a2d      = (const float*)d_in[15];
    const float* b2       = (const float*)d_in[16];
    const float* rel_emb  = (const float*)d_in[17];
    float* out = (float*)d_out;

    const int* src = eidx;
    const int* dst = eidx + EE;

    // CSR build + disease-degree histogram
    zero_kernel<<<(NN + 255) / 256, 256>>>();
    hist_deg_kernel<<<(EE + 255) / 256, 256>>>(dst);
    cnt_hist_kernel<<<(3 * ER + 255) / 256, 256>>>(reledge);
    partial_kernel<<<PB, 256>>>();
    rowptr_kernel<<<PB, 512>>>();
    scatter_kernel<<<(EE + 255) / 256, 256>>>(src, dst);

    dim3 ggrid((NN + BM - 1) / BM, 2);
    int nwBlocks = (NN * 32 + 255) / 256;  // warp-per-node kernels

    // Layer 1
    gemm_tc<1><<<ggrid, 256>>>(x, W1, NN);
    sdots_kernel<<<nwBlocks, 256>>>(a1s, a1d);
    gat_aggregate_kernel<1><<<nwBlocks, 256>>>(b1);

    // Layer 2
    gemm_tc<2><<<ggrid, 256>>>(nullptr, W2, NN);
    sdots_kernel<<<nwBlocks, 256>>>(a2s, a2d);
    gat_aggregate_kernel<2><<<nwBlocks, 256>>>(b2);

    // Sequential disease-embedding modification + decode
    scan_seq_kernel<<<1, 256>>>(head, rel, g2l, simnb, simw);
    decode_kernel<<<(BB * 32 + 255) / 256, 256>>>(head, rel, tail, rel_emb, out);
}